// round 5
// baseline (speedup 1.0000x reference)
#include <cuda_runtime.h>
#include <cuda_fp16.h>
#include <math.h>
#include <float.h>
#include <stdint.h>

// FILIP loss. B=64, T=64, I=196, D=512.
// sim = text[4096,512] @ vision[12544,512]^T with fused row/col max epilogue.
// fp16 HMMA GEMM, 256x128 CTA tile, 512 threads, 4-stage cp.async pipeline.

#define D_K   512
#define M_TOT 4096
#define N_TOT 12544
#define B_SZ  64
#define I_TOK 196

#define BM 256
#define BN 128
#define BK 64                       // fp16 -> 128 bytes/row (SW128 atom)
#define NCHUNK (D_K / BK)           // 8
#define NSTAGE 4
#define A_STAGE_BYTES (BM * 128)    // 32768
#define B_STAGE_BYTES (BN * 128)    // 16384
#define STAGE_BYTES  (A_STAGE_BYTES + B_STAGE_BYTES)   // 49152
#define DSMEM_BYTES  (NSTAGE * STAGE_BYTES)            // 196608

#define NT_M (M_TOT / BM)           // 16
#define NT_N (N_TOT / BN)           // 98
#define PANEL_W 8

#define ENC_NEG 0x00800000u

#define SWZ128(o) ((o) ^ (((o) >> 3) & 0x70))

__device__ __forceinline__ uint32_t smem_u32(const void* p) {
    uint32_t a;
    asm("{ .reg .u64 t; cvta.to.shared.u64 t, %1; cvt.u32.u64 %0, t; }" : "=r"(a) : "l"(p));
    return a;
}
__device__ __forceinline__ unsigned enc_f(float f) {
    unsigned u = __float_as_uint(f);
    return (u & 0x80000000u) ? ~u : (u | 0x80000000u);
}
__device__ __forceinline__ float dec_f(unsigned u) {
    return __uint_as_float((u & 0x80000000u) ? (u & 0x7FFFFFFFu) : ~u);
}

__device__ __forceinline__ void cp_async16(uint32_t saddr, const void* gptr) {
    asm volatile("cp.async.cg.shared.global [%0], [%1], 16;" :: "r"(saddr), "l"(gptr));
}
__device__ __forceinline__ void cp_commit() {
    asm volatile("cp.async.commit_group;");
}
__device__ __forceinline__ void ldmx4(uint32_t* r, uint32_t addr) {
    asm volatile("ldmatrix.sync.aligned.m8n8.x4.shared.b16 {%0,%1,%2,%3}, [%4];"
        : "=r"(r[0]), "=r"(r[1]), "=r"(r[2]), "=r"(r[3]) : "r"(addr));
}
__device__ __forceinline__ void mma16816(float* c, const uint32_t* a, uint32_t b0, uint32_t b1) {
    asm volatile("mma.sync.aligned.m16n8k16.row.col.f32.f16.f16.f32 "
        "{%0,%1,%2,%3}, {%4,%5,%6,%7}, {%8,%9}, {%0,%1,%2,%3};"
        : "+f"(c[0]), "+f"(c[1]), "+f"(c[2]), "+f"(c[3])
        : "r"(a[0]), "r"(a[1]), "r"(a[2]), "r"(a[3]), "r"(b0), "r"(b1));
}

// ---------------- scratch ----------------
__device__ __half  Aq[(size_t)M_TOT * D_K];   // text  fp16
__device__ __half  Bq[(size_t)N_TOT * D_K];   // vision fp16
__device__ unsigned g_rowmax[M_TOT * B_SZ];   // [m][y] encoded max over i
__device__ float    g_colmax[B_SZ * N_TOT];   // [x][n] max over t
__device__ float    g_t2i[B_SZ * B_SZ];
__device__ float    g_i2t[B_SZ * B_SZ];

// convert + init fused
__global__ void convert_kernel(const float* __restrict__ text,
                               const float* __restrict__ vision) {
    const int TP = M_TOT * D_K / 2;
    const int VP = N_TOT * D_K / 2;
    int idx = blockIdx.x * blockDim.x + threadIdx.x;
    if (idx < TP) {
        float2 v = ((const float2*)text)[idx];
        ((half2*)Aq)[idx] = __floats2half2_rn(v.x, v.y);
    } else if (idx < TP + VP) {
        float2 v = ((const float2*)vision)[idx - TP];
        ((half2*)Bq)[idx - TP] = __floats2half2_rn(v.x, v.y);
    }
    if (idx < M_TOT * B_SZ) g_rowmax[idx] = ENC_NEG;
}

// ---------------- fused HMMA GEMM + max epilogue ----------------
__global__ void __launch_bounds__(512, 1)
gemm_max_kernel(const unsigned char* __restrict__ tmask,
                const unsigned char* __restrict__ vmask)
{
    extern __shared__ char dsm[];
    __shared__ unsigned s_row[BM][2];     // rowmax per local m, per y-seg
    __shared__ unsigned s_col[4][BN];     // colmax per x-subblock (64 rows), per n
    __shared__ unsigned char s_tm[BM], s_vm[BN];

    const int tid = threadIdx.x;
    const int w = tid >> 5, lane = tid & 31;
    const int g = lane >> 2, tig = lane & 3;
    const int wm = w >> 2, wn = w & 3;     // warps: 4 (m) x 4 (n); warp tile 64x32

    // panel rasterization: panels of (16 m-tiles x 8 n-tiles) = 128 CTAs
    int bid = blockIdx.x;
    int tm_i, tn_i;
    if (bid < (NT_N / PANEL_W) * NT_M * PANEL_W) {       // 12 full panels
        int p = bid >> 7, idx = bid & 127;
        tn_i = p * PANEL_W + (idx >> 4);
        tm_i = idx & 15;
    } else {
        int e = bid - (NT_N / PANEL_W) * NT_M * PANEL_W;
        tn_i = (NT_N / PANEL_W) * PANEL_W + (e >> 4);
        tm_i = e & 15;
    }
    const int m0 = tm_i * BM;
    const int n0 = tn_i * BN;

    const __half* gA = Aq + (size_t)m0 * D_K;
    const __half* gB = Bq + (size_t)n0 * D_K;
    const uint32_t smem_base = smem_u32(dsm);

    // loader mapping (512 threads): A 256 rows x 8 f4 -> 4 f4/thread
    //                               B 128 rows x 8 f4 -> 2 f4/thread
    const int arow = tid >> 1;            // 0..255
    const int ac0  = (tid & 1) << 2;      // 0 or 4
    const int brow = tid >> 2;            // 0..127
    const int bc0  = (tid & 3) << 1;      // 0,2,4,6

    auto load_stage = [&](int ch, int s) {
        const uint32_t As = smem_base + s * STAGE_BYTES;
        const uint32_t Bs = As + A_STAGE_BYTES;
        const __half* gAc = gA + (size_t)arow * D_K + ch * BK;
        const __half* gBc = gB + (size_t)brow * D_K + ch * BK;
#pragma unroll
        for (int j = 0; j < 4; j++) {
            int c = ac0 + j;
            cp_async16(As + SWZ128(arow * 128 + c * 16), gAc + c * 8);
        }
#pragma unroll
        for (int j = 0; j < 2; j++) {
            int c = bc0 + j;
            cp_async16(Bs + SWZ128(brow * 128 + c * 16), gBc + c * 8);
        }
        cp_commit();
    };

    // per-lane raw smem offsets for ldmatrix (before swizzle, before kk)
    uint32_t rawA[4], rawB[2];
#pragma unroll
    for (int mt = 0; mt < 4; mt++)
        rawA[mt] = (wm * 64 + mt * 16 + (lane & 15)) * 128 + (lane >> 4) * 16;
#pragma unroll
    for (int ntp = 0; ntp < 2; ntp++) {
        int nrow = wn * 32 + ntp * 16 + (lane & 7) + ((lane >> 4) << 3);
        rawB[ntp] = nrow * 128 + (((lane >> 3) & 1) ? 16 : 0);
    }

    float acc[4][4][4];
#pragma unroll
    for (int mt = 0; mt < 4; mt++)
#pragma unroll
        for (int nt = 0; nt < 4; nt++)
#pragma unroll
            for (int i = 0; i < 4; i++) acc[mt][nt][i] = 0.f;

    // prologue: fill 3 of 4 stages
    load_stage(0, 0);
    load_stage(1, 1);
    load_stage(2, 2);

#pragma unroll 1
    for (int ch = 0; ch < NCHUNK; ch++) {
        if (ch + 3 < NCHUNK) { asm volatile("cp.async.wait_group 2;"); }
        else                 { asm volatile("cp.async.wait_group 0;"); }
        __syncthreads();
        if (ch + 3 < NCHUNK) load_stage(ch + 3, (ch + 3) % NSTAGE);

        const uint32_t As = smem_base + (ch % NSTAGE) * STAGE_BYTES;
        const uint32_t Bs = As + A_STAGE_BYTES;
#pragma unroll
        for (int kk = 0; kk < 4; kk++) {
            uint32_t a[4][4], b[2][4];
#pragma unroll
            for (int mt = 0; mt < 4; mt++)
                ldmx4(a[mt], As + SWZ128(rawA[mt] + kk * 32));
#pragma unroll
            for (int ntp = 0; ntp < 2; ntp++)
                ldmx4(b[ntp], Bs + SWZ128(rawB[ntp] + kk * 32));
#pragma unroll
            for (int mt = 0; mt < 4; mt++) {
                mma16816(acc[mt][0], a[mt], b[0][0], b[0][1]);
                mma16816(acc[mt][1], a[mt], b[0][2], b[0][3]);
                mma16816(acc[mt][2], a[mt], b[1][0], b[1][1]);
                mma16816(acc[mt][3], a[mt], b[1][2], b[1][3]);
            }
        }
    }

    // ---------------- fused max epilogue ----------------
    for (int e = tid; e < BM * 2; e += 512) ((unsigned*)s_row)[e] = ENC_NEG;
    for (int e = tid; e < 4 * BN; e += 512) ((unsigned*)s_col)[e] = ENC_NEG;
    if (tid < BM) s_tm[tid] = tmask[m0 + tid];
    else if (tid < BM + BN) s_vm[tid - BM] = vmask[n0 + (tid - BM)];
    __syncthreads();

    const int y0 = n0 / I_TOK;
    const int b1 = (y0 + 1) * I_TOK - n0;     // first col of seg1 (may be >=BN)

    int ncol[4][2]; bool vm_ok[4][2]; bool seg1[4][2];
#pragma unroll
    for (int nt = 0; nt < 4; nt++)
#pragma unroll
        for (int cc = 0; cc < 2; cc++) {
            int nl = wn * 32 + nt * 8 + 2 * tig + cc;
            ncol[nt][cc] = nl;
            vm_ok[nt][cc] = s_vm[nl] != 0;
            seg1[nt][cc] = nl >= b1;
        }
    int mrow[4][2]; bool tm_ok[4][2];
#pragma unroll
    for (int mt = 0; mt < 4; mt++)
#pragma unroll
        for (int gg = 0; gg < 2; gg++) {
            int ml = wm * 64 + mt * 16 + g + gg * 8;
            mrow[mt][gg] = ml;
            tm_ok[mt][gg] = s_tm[ml] != 0;
        }

    // rowmax: per (mt,gg) per seg, reduce across quad (cols), lane tig==0 atomics
#pragma unroll
    for (int mt = 0; mt < 4; mt++)
#pragma unroll
        for (int gg = 0; gg < 2; gg++) {
            float mx0 = -FLT_MAX, mx1 = -FLT_MAX;
#pragma unroll
            for (int nt = 0; nt < 4; nt++)
#pragma unroll
                for (int cc = 0; cc < 2; cc++) {
                    if (!vm_ok[nt][cc]) continue;
                    float v = acc[mt][nt][gg * 2 + cc];
                    if (seg1[nt][cc]) mx1 = fmaxf(mx1, v);
                    else              mx0 = fmaxf(mx0, v);
                }
#pragma unroll
            for (int o = 1; o <= 2; o <<= 1) {
                mx0 = fmaxf(mx0, __shfl_xor_sync(0xffffffffu, mx0, o));
                mx1 = fmaxf(mx1, __shfl_xor_sync(0xffffffffu, mx1, o));
            }
            if (tig == 0) {
                if (mx0 > -FLT_MAX) atomicMax(&s_row[mrow[mt][gg]][0], enc_f(mx0));
                if (mx1 > -FLT_MAX) atomicMax(&s_row[mrow[mt][gg]][1], enc_f(mx1));
            }
        }

    // colmax: per (nt,cc), max over this lane's 8 rows (tmask), reduce across g
    const int xh = wm;   // warp spans one 64-row x-subblock
#pragma unroll
    for (int nt = 0; nt < 4; nt++)
#pragma unroll
        for (int cc = 0; cc < 2; cc++) {
            float mx = -FLT_MAX;
#pragma unroll
            for (int mt = 0; mt < 4; mt++)
#pragma unroll
                for (int gg = 0; gg < 2; gg++)
                    if (tm_ok[mt][gg]) mx = fmaxf(mx, acc[mt][nt][gg * 2 + cc]);
#pragma unroll
            for (int o = 4; o <= 16; o <<= 1)
                mx = fmaxf(mx, __shfl_xor_sync(0xffffffffu, mx, o));
            if (g == 0 && mx > -FLT_MAX)
                atomicMax(&s_col[xh][ncol[nt][cc]], enc_f(mx));
        }
    __syncthreads();

    // flush
    const int ylast = (n0 + BN - 1) / I_TOK;
    {
        const int rr = tid >> 1, seg = tid & 1;    // 512 = BM*2
        if (y0 + seg <= ylast) {
            const unsigned v = s_row[rr][seg];
            if (v != ENC_NEG)
                atomicMax(&g_rowmax[(size_t)(m0 + rr) * B_SZ + y0 + seg], v);
        }
    }
    {
        const int hh = tid >> 7, col = tid & 127;  // 512 = 4*BN
        g_colmax[(size_t)((m0 >> 6) + hh) * N_TOT + n0 + col] = dec_f(s_col[hh][col]);
    }
}

// ---------------- means: one block per (x,y), 64 threads ----------------
__global__ void means_kernel(const unsigned char* __restrict__ tmask,
                             const unsigned char* __restrict__ vmask)
{
    __shared__ float red[4][2];
    const int x = blockIdx.x, y = blockIdx.y;
    const int tid = threadIdx.x;   // 64
    const float temp = expf(logf((float)(1.0 / 0.07)));

    float s2 = 0.f, c2 = 0.f;
    for (int i = tid; i < I_TOK; i += 64) {
        if (vmask[y * I_TOK + i]) {
            s2 += g_colmax[(size_t)x * N_TOT + y * I_TOK + i];
            c2 += 1.f;
        }
    }
    float s1 = 0.f, c1 = 0.f;
    {
        int t = tid;
        if (tmask[x * B_SZ + t]) {
            s1 = dec_f(g_rowmax[(size_t)(x * B_SZ + t) * B_SZ + y]);
            c1 = 1.f;
        }
    }
#pragma unroll
    for (int o = 16; o > 0; o >>= 1) {
        s1 += __shfl_xor_sync(0xffffffffu, s1, o);
        c1 += __shfl_xor_sync(0xffffffffu, c1, o);
        s2 += __shfl_xor_sync(0xffffffffu, s2, o);
        c2 += __shfl_xor_sync(0xffffffffu, c2, o);
    }
    const int wid = tid >> 5;
    if ((tid & 31) == 0) {
        red[0][wid] = s1; red[1][wid] = c1;
        red[2][wid] = s2; red[3][wid] = c2;
    }
    __syncthreads();
    if (tid == 0) {
        float S1 = red[0][0] + red[0][1], C1 = red[1][0] + red[1][1];
        float S2 = red[2][0] + red[2][1], C2 = red[3][0] + red[3][1];
        g_t2i[x * B_SZ + y] = temp * (S1 / fmaxf(C1, 1e-6f));
        g_i2t[x * B_SZ + y] = temp * (S2 / fmaxf(C2, 1e-6f));
    }
}

// ---------------- finalize: single block, 1024 threads ----------------
__global__ void finalize_kernel(float* __restrict__ out)
{
    __shared__ float se1[B_SZ], se2[B_SZ], sh1[B_SZ], sh2[B_SZ];
    const int tid = threadIdx.x;
    const int t = tid >> 4, j = tid & 15;

    float p1 = 0.f, p2 = 0.f;
    for (int k = j; k < B_SZ; k += 16) {
        p1 += expf(g_t2i[t * B_SZ + k]);
        p2 += expf(g_i2t[k * B_SZ + t]);
    }
#pragma unroll
    for (int o = 8; o > 0; o >>= 1) {
        p1 += __shfl_xor_sync(0xffffffffu, p1, o);
        p2 += __shfl_xor_sync(0xffffffffu, p2, o);
    }
    if (j == 0) { se1[t] = p1; se2[t] = p2; }
    __syncthreads();

    if (tid < B_SZ) {
        const float d1 = expf(g_t2i[tid * B_SZ + tid]);
        const float d2 = expf(g_i2t[tid * B_SZ + tid]);
        sh1[tid] = -logf(d1 + 1e-20f) + logf(se1[tid] + 1e-20f);
        sh2[tid] = -logf(d2 + 1e-20f) + logf(se2[tid] + 1e-20f);
    }
    __syncthreads();
    if (tid == 0) {
        float a = 0.f, b = 0.f;
        for (int i = 0; i < B_SZ; i++) { a += sh1[i]; b += sh2[i]; }
        a *= (1.f / 64.f);
        b *= (1.f / 64.f);
        out[0] = 0.5f * (a + b);
        out[1] = a;
        out[2] = b;
    }
}

extern "C" void kernel_launch(void* const* d_in, const int* in_sizes, int n_in,
                              void* d_out, int out_size)
{
    const float *vision, *text;
    const unsigned char *vmask, *tmask;
    if (in_sizes[0] == N_TOT * D_K) {
        vision = (const float*)d_in[0];
        text   = (const float*)d_in[1];
    } else {
        vision = (const float*)d_in[1];
        text   = (const float*)d_in[0];
    }
    if (in_sizes[2] == N_TOT) {
        vmask = (const unsigned char*)d_in[2];
        tmask = (const unsigned char*)d_in[3];
    } else {
        vmask = (const unsigned char*)d_in[3];
        tmask = (const unsigned char*)d_in[2];
    }
    float* out = (float*)d_out;

    cudaFuncSetAttribute(gemm_max_kernel,
                         cudaFuncAttributeMaxDynamicSharedMemorySize, DSMEM_BYTES);

    const int pairs = (M_TOT + N_TOT) * D_K / 2;
    convert_kernel<<<(pairs + 255) / 256, 256>>>(text, vision);
    gemm_max_kernel<<<NT_M * NT_N, 512, DSMEM_BYTES>>>(tmask, vmask);
    dim3 mgrid(B_SZ, B_SZ);
    means_kernel<<<mgrid, 64>>>(tmask, vmask);
    finalize_kernel<<<1, 1024>>>(out);
}

// round 6
// speedup vs baseline: 1.5193x; 1.5193x over previous
#include <cuda_runtime.h>
#include <cuda_fp16.h>
#include <math.h>
#include <float.h>
#include <stdint.h>

// FILIP loss. B=64, T=64, I=196, D=512.
// sim = text[4096,512] @ vision[12544,512]^T with fused row/col max epilogue.
// fp16 HMMA GEMM. Loader rebuilt around cp.async.bulk (UBLKCP): convert
// pre-pass stores A/B in tiled+SW128-swizzled gmem layout; GEMM bulk-copies
// one 16KB tile per instruction into a 3-stage mbarrier pipeline.

#define D_K   512
#define M_TOT 4096
#define N_TOT 12544
#define B_SZ  64
#define I_TOK 196

#define BM 128
#define BN 128
#define BK 64                        // fp16 -> 128 bytes/row (SW128 atom)
#define NCHUNK (D_K / BK)            // 8
#define NSTAGE 3
#define TILE_BYTES 16384             // 128 rows x 128 B
#define STAGE_BYTES (2 * TILE_BYTES) // A + B
#define DSMEM_BYTES (NSTAGE * STAGE_BYTES)   // 98304 -> 2 CTAs/SM

#define NT_M (M_TOT / BM)            // 32
#define NT_N (N_TOT / BN)            // 98
#define PANEL_W 4

#define ENC_NEG 0x00800000u
#define SWZ128(o) ((o) ^ (((o) >> 3) & 0x70))

__device__ __forceinline__ uint32_t smem_u32(const void* p) {
    uint32_t a;
    asm("{ .reg .u64 t; cvta.to.shared.u64 t, %1; cvt.u32.u64 %0, t; }" : "=r"(a) : "l"(p));
    return a;
}
__device__ __forceinline__ unsigned enc_f(float f) {
    unsigned u = __float_as_uint(f);
    return (u & 0x80000000u) ? ~u : (u | 0x80000000u);
}
__device__ __forceinline__ float dec_f(unsigned u) {
    return __uint_as_float((u & 0x80000000u) ? (u & 0x7FFFFFFFu) : ~u);
}

#define MBAR_INIT(mb, c) asm volatile("mbarrier.init.shared.b64 [%0], %1;" :: "r"(mb), "r"(c) : "memory")
#define MBAR_ARRIVE(mb)  asm volatile("mbarrier.arrive.shared.b64 _, [%0];" :: "r"(mb) : "memory")
#define MBAR_EXPECT_TX(mb, n) asm volatile("mbarrier.arrive.expect_tx.shared.b64 _, [%0], %1;" :: "r"(mb), "r"(n) : "memory")
#define FENCE_ASYNC() asm volatile("fence.proxy.async.shared::cta;" ::: "memory")

#define MBAR_WAIT(mb, par) do { \
    uint32_t _m = (mb), _p = (par), _d; \
    asm volatile("{ .reg .pred p; mbarrier.try_wait.parity.acquire.cta.shared::cta.b64 p, [%1], %2; selp.b32 %0,1,0,p; }" \
        : "=r"(_d) : "r"(_m), "r"(_p) : "memory"); \
    if (!_d) { \
        asm volatile("{ .reg .pred P1; WL_%=: mbarrier.try_wait.parity.acquire.cta.shared::cta.b64 P1, [%0], %1, 0x989680; @P1 bra.uni WD_%=; bra.uni WL_%=; WD_%=: }" \
            :: "r"(_m), "r"(_p) : "memory"); \
    } } while (0)

__device__ __forceinline__ void bulk_g2s(uint32_t dst, const void* src, uint32_t mb) {
    asm volatile("cp.async.bulk.shared::cluster.global.mbarrier::complete_tx::bytes [%0], [%1], %2, [%3];"
        :: "r"(dst), "l"(__cvta_generic_to_global(src)), "r"((uint32_t)TILE_BYTES), "r"(mb) : "memory");
}

__device__ __forceinline__ void ldmx4(uint32_t* r, uint32_t addr) {
    asm volatile("ldmatrix.sync.aligned.m8n8.x4.shared.b16 {%0,%1,%2,%3}, [%4];"
        : "=r"(r[0]), "=r"(r[1]), "=r"(r[2]), "=r"(r[3]) : "r"(addr));
}
__device__ __forceinline__ void mma16816(float* c, const uint32_t* a, uint32_t b0, uint32_t b1) {
    asm volatile("mma.sync.aligned.m16n8k16.row.col.f32.f16.f16.f32 "
        "{%0,%1,%2,%3}, {%4,%5,%6,%7}, {%8,%9}, {%0,%1,%2,%3};"
        : "+f"(c[0]), "+f"(c[1]), "+f"(c[2]), "+f"(c[3])
        : "r"(a[0]), "r"(a[1]), "r"(a[2]), "r"(a[3]), "r"(b0), "r"(b1));
}

// ---------------- scratch ----------------
// Tiled + swizzled fp16 layout: tile index = (rowblk * 8 + ch), each tile 16KB.
__device__ __half  Aq[(size_t)M_TOT * D_K];
__device__ __half  Bq[(size_t)N_TOT * D_K];
__device__ unsigned g_rowmax[M_TOT * B_SZ];   // [m][y] encoded max over i
__device__ float    g_colmax[B_SZ * N_TOT];   // [x][n] max over t
__device__ float    g_t2i[B_SZ * B_SZ];
__device__ float    g_i2t[B_SZ * B_SZ];

// convert (fp32 -> fp16, tiled + SW128 swizzled) + rowmax init, fused
__global__ void convert_kernel(const float* __restrict__ text,
                               const float* __restrict__ vision) {
    const int TP = M_TOT * D_K / 2;
    const int VP = N_TOT * D_K / 2;
    int idx = blockIdx.x * blockDim.x + threadIdx.x;
    if (idx < TP) {
        float2 v = ((const float2*)text)[idx];
        int e = idx * 2;
        int m = e >> 9, k = e & 511;
        int tile = (m >> 7) * NCHUNK + (k >> 6);
        int off = (m & 127) * 128 + (k & 63) * 2;
        *(half2*)((char*)Aq + (size_t)tile * TILE_BYTES + SWZ128(off)) =
            __floats2half2_rn(v.x, v.y);
    } else if (idx < TP + VP) {
        int p = idx - TP;
        float2 v = ((const float2*)vision)[p];
        int e = p * 2;
        int n = e >> 9, k = e & 511;
        int tile = (n >> 7) * NCHUNK + (k >> 6);
        int off = (n & 127) * 128 + (k & 63) * 2;
        *(half2*)((char*)Bq + (size_t)tile * TILE_BYTES + SWZ128(off)) =
            __floats2half2_rn(v.x, v.y);
    }
    if (idx < M_TOT * B_SZ) g_rowmax[idx] = ENC_NEG;
}

// ---------------- fused HMMA GEMM + max epilogue ----------------
__global__ void __launch_bounds__(256, 2)
gemm_max_kernel(const unsigned char* __restrict__ tmask,
                const unsigned char* __restrict__ vmask)
{
    extern __shared__ char dsm[];
    __shared__ alignas(8) unsigned long long s_bar[2 * NSTAGE]; // full[3], empty[3]
    __shared__ unsigned s_row[BM][2];
    __shared__ unsigned s_col[2][BN];
    __shared__ unsigned char s_tm[BM], s_vm[BN];

    const int tid = threadIdx.x;
    const int w = tid >> 5, lane = tid & 31;
    const int g = lane >> 2, tig = lane & 3;
    const int wm = w >> 2, wn = w & 3;     // warps: 2 (m) x 4 (n); warp tile 64x32

    // panel rasterization: panels of (32 m-tiles x 4 n-tiles) = 128 CTAs
    int bid = blockIdx.x;
    int tm_i, tn_i;
    if (bid < (NT_N / PANEL_W) * NT_M * PANEL_W) {
        int p = bid >> 7, idx = bid & 127;
        tn_i = p * PANEL_W + (idx >> 5);
        tm_i = idx & 31;
    } else {
        int e = bid - (NT_N / PANEL_W) * NT_M * PANEL_W;
        tn_i = (NT_N / PANEL_W) * PANEL_W + (e >> 5);
        tm_i = e & 31;
    }
    const int m0 = tm_i * BM;
    const int n0 = tn_i * BN;

    const char* gAt = (const char*)Aq + (size_t)(tm_i * NCHUNK) * TILE_BYTES;
    const char* gBt = (const char*)Bq + (size_t)(tn_i * NCHUNK) * TILE_BYTES;
    const uint32_t smem_base = smem_u32(dsm);
    const uint32_t bar0 = smem_u32(&s_bar[0]);

    // barrier init + prologue bulk issues for stages 0..2
    if (tid == 0) {
#pragma unroll
        for (int s = 0; s < NSTAGE; s++) {
            MBAR_INIT(bar0 + s * 8, 1);                       // full[s]
            MBAR_INIT(bar0 + (NSTAGE + s) * 8, 256);          // empty[s]
        }
        FENCE_ASYNC();
    }
    __syncthreads();
    if (tid == 0) {
#pragma unroll
        for (int c = 0; c < NSTAGE; c++) {
            const uint32_t fb = bar0 + c * 8;
            MBAR_EXPECT_TX(fb, STAGE_BYTES);
            bulk_g2s(smem_base + c * STAGE_BYTES,             gAt + (size_t)c * TILE_BYTES, fb);
            bulk_g2s(smem_base + c * STAGE_BYTES + TILE_BYTES, gBt + (size_t)c * TILE_BYTES, fb);
        }
    }

    // per-lane raw smem offsets for ldmatrix (before swizzle, before kk)
    uint32_t rawA[4], rawB[2];
#pragma unroll
    for (int mt = 0; mt < 4; mt++)
        rawA[mt] = (wm * 64 + mt * 16 + (lane & 15)) * 128 + (lane >> 4) * 16;
#pragma unroll
    for (int ntp = 0; ntp < 2; ntp++) {
        int nrow = wn * 32 + ntp * 16 + (lane & 7) + ((lane >> 4) << 3);
        rawB[ntp] = nrow * 128 + (((lane >> 3) & 1) ? 16 : 0);
    }

    float acc[4][4][4];
#pragma unroll
    for (int mt = 0; mt < 4; mt++)
#pragma unroll
        for (int nt = 0; nt < 4; nt++)
#pragma unroll
            for (int i = 0; i < 4; i++) acc[mt][nt][i] = 0.f;

#pragma unroll 1
    for (int ch = 0; ch < NCHUNK; ch++) {
        const int s = ch % NSTAGE;
        const int grp = ch / NSTAGE;
        const uint32_t full_b  = bar0 + s * 8;
        const uint32_t empty_b = bar0 + (NSTAGE + s) * 8;

        MBAR_WAIT(full_b, grp & 1);

        const uint32_t As = smem_base + s * STAGE_BYTES;
        const uint32_t Bs = As + TILE_BYTES;
#pragma unroll
        for (int kk = 0; kk < 4; kk++) {
            uint32_t a[4][4], b[2][4];
#pragma unroll
            for (int mt = 0; mt < 4; mt++)
                ldmx4(a[mt], As + SWZ128(rawA[mt] + kk * 32));
#pragma unroll
            for (int ntp = 0; ntp < 2; ntp++)
                ldmx4(b[ntp], Bs + SWZ128(rawB[ntp] + kk * 32));
#pragma unroll
            for (int mt = 0; mt < 4; mt++) {
                mma16816(acc[mt][0], a[mt], b[0][0], b[0][1]);
                mma16816(acc[mt][1], a[mt], b[0][2], b[0][3]);
                mma16816(acc[mt][2], a[mt], b[1][0], b[1][1]);
                mma16816(acc[mt][3], a[mt], b[1][2], b[1][3]);
            }
        }

        if (ch + NSTAGE < NCHUNK) {
            MBAR_ARRIVE(empty_b);
            if (tid == 0) {
                MBAR_WAIT(empty_b, grp & 1);   // all 256 consumed stage s
                const int c2 = ch + NSTAGE;
                MBAR_EXPECT_TX(full_b, STAGE_BYTES);
                bulk_g2s(As, gAt + (size_t)c2 * TILE_BYTES, full_b);
                bulk_g2s(Bs, gBt + (size_t)c2 * TILE_BYTES, full_b);
            }
        }
    }

    // ---------------- fused max epilogue ----------------
    for (int e = tid; e < BM * 2; e += 256) ((unsigned*)s_row)[e] = ENC_NEG;
    for (int e = tid; e < 2 * BN; e += 256) ((unsigned*)s_col)[e] = ENC_NEG;
    if (tid < BM) s_tm[tid] = tmask[m0 + tid];
    else          s_vm[tid - BM] = vmask[n0 + (tid - BM)];
    __syncthreads();

    const int y0 = n0 / I_TOK;
    const int b1 = (y0 + 1) * I_TOK - n0;

    int ncol[4][2]; bool vm_ok[4][2]; bool seg1[4][2];
#pragma unroll
    for (int nt = 0; nt < 4; nt++)
#pragma unroll
        for (int cc = 0; cc < 2; cc++) {
            int nl = wn * 32 + nt * 8 + 2 * tig + cc;
            ncol[nt][cc] = nl;
            vm_ok[nt][cc] = s_vm[nl] != 0;
            seg1[nt][cc] = nl >= b1;
        }
    int mrow[4][2]; bool tm_ok[4][2];
#pragma unroll
    for (int mt = 0; mt < 4; mt++)
#pragma unroll
        for (int gg = 0; gg < 2; gg++) {
            int ml = wm * 64 + mt * 16 + g + gg * 8;
            mrow[mt][gg] = ml;
            tm_ok[mt][gg] = s_tm[ml] != 0;
        }

#pragma unroll
    for (int mt = 0; mt < 4; mt++)
#pragma unroll
        for (int gg = 0; gg < 2; gg++) {
            float mx0 = -FLT_MAX, mx1 = -FLT_MAX;
#pragma unroll
            for (int nt = 0; nt < 4; nt++)
#pragma unroll
                for (int cc = 0; cc < 2; cc++) {
                    if (!vm_ok[nt][cc]) continue;
                    float v = acc[mt][nt][gg * 2 + cc];
                    if (seg1[nt][cc]) mx1 = fmaxf(mx1, v);
                    else              mx0 = fmaxf(mx0, v);
                }
#pragma unroll
            for (int o = 1; o <= 2; o <<= 1) {
                mx0 = fmaxf(mx0, __shfl_xor_sync(0xffffffffu, mx0, o));
                mx1 = fmaxf(mx1, __shfl_xor_sync(0xffffffffu, mx1, o));
            }
            if (tig == 0) {
                if (mx0 > -FLT_MAX) atomicMax(&s_row[mrow[mt][gg]][0], enc_f(mx0));
                if (mx1 > -FLT_MAX) atomicMax(&s_row[mrow[mt][gg]][1], enc_f(mx1));
            }
        }

    const int xh = wm;
#pragma unroll
    for (int nt = 0; nt < 4; nt++)
#pragma unroll
        for (int cc = 0; cc < 2; cc++) {
            float mx = -FLT_MAX;
#pragma unroll
            for (int mt = 0; mt < 4; mt++)
#pragma unroll
                for (int gg = 0; gg < 2; gg++)
                    if (tm_ok[mt][gg]) mx = fmaxf(mx, acc[mt][nt][gg * 2 + cc]);
#pragma unroll
            for (int o = 4; o <= 16; o <<= 1)
                mx = fmaxf(mx, __shfl_xor_sync(0xffffffffu, mx, o));
            if (g == 0 && mx > -FLT_MAX)
                atomicMax(&s_col[xh][ncol[nt][cc]], enc_f(mx));
        }
    __syncthreads();

    const int ylast = (n0 + BN - 1) / I_TOK;
    for (int e = tid; e < BM * 2; e += 256) {
        const int rr = e >> 1, seg = e & 1;
        if (y0 + seg > ylast) continue;
        const unsigned v = s_row[rr][seg];
        if (v != ENC_NEG)
            atomicMax(&g_rowmax[(size_t)(m0 + rr) * B_SZ + y0 + seg], v);
    }
    for (int e = tid; e < 2 * BN; e += 256) {
        const int hh = e >> 7, col = e & 127;
        g_colmax[(size_t)((m0 >> 6) + hh) * N_TOT + n0 + col] = dec_f(s_col[hh][col]);
    }
}

// ---------------- means: one block per (x,y), 64 threads ----------------
__global__ void means_kernel(const unsigned char* __restrict__ tmask,
                             const unsigned char* __restrict__ vmask)
{
    __shared__ float red[4][2];
    const int x = blockIdx.x, y = blockIdx.y;
    const int tid = threadIdx.x;
    const float temp = expf(logf((float)(1.0 / 0.07)));

    float s2 = 0.f, c2 = 0.f;
    for (int i = tid; i < I_TOK; i += 64) {
        if (vmask[y * I_TOK + i]) {
            s2 += g_colmax[(size_t)x * N_TOT + y * I_TOK + i];
            c2 += 1.f;
        }
    }
    float s1 = 0.f, c1 = 0.f;
    if (tmask[x * B_SZ + tid]) {
        s1 = dec_f(g_rowmax[(size_t)(x * B_SZ + tid) * B_SZ + y]);
        c1 = 1.f;
    }
#pragma unroll
    for (int o = 16; o > 0; o >>= 1) {
        s1 += __shfl_xor_sync(0xffffffffu, s1, o);
        c1 += __shfl_xor_sync(0xffffffffu, c1, o);
        s2 += __shfl_xor_sync(0xffffffffu, s2, o);
        c2 += __shfl_xor_sync(0xffffffffu, c2, o);
    }
    const int wid = tid >> 5;
    if ((tid & 31) == 0) {
        red[0][wid] = s1; red[1][wid] = c1;
        red[2][wid] = s2; red[3][wid] = c2;
    }
    __syncthreads();
    if (tid == 0) {
        float S1 = red[0][0] + red[0][1], C1 = red[1][0] + red[1][1];
        float S2 = red[2][0] + red[2][1], C2 = red[3][0] + red[3][1];
        g_t2i[x * B_SZ + y] = temp * (S1 / fmaxf(C1, 1e-6f));
        g_i2t[x * B_SZ + y] = temp * (S2 / fmaxf(C2, 1e-6f));
    }
}

// ---------------- finalize: single block, 1024 threads ----------------
__global__ void finalize_kernel(float* __restrict__ out)
{
    __shared__ float se1[B_SZ], se2[B_SZ], sh1[B_SZ], sh2[B_SZ];
    const int tid = threadIdx.x;
    const int t = tid >> 4, j = tid & 15;

    float p1 = 0.f, p2 = 0.f;
    for (int k = j; k < B_SZ; k += 16) {
        p1 += expf(g_t2i[t * B_SZ + k]);
        p2 += expf(g_i2t[k * B_SZ + t]);
    }
#pragma unroll
    for (int o = 8; o > 0; o >>= 1) {
        p1 += __shfl_xor_sync(0xffffffffu, p1, o);
        p2 += __shfl_xor_sync(0xffffffffu, p2, o);
    }
    if (j == 0) { se1[t] = p1; se2[t] = p2; }
    __syncthreads();

    if (tid < B_SZ) {
        const float d1 = expf(g_t2i[tid * B_SZ + tid]);
        const float d2 = expf(g_i2t[tid * B_SZ + tid]);
        sh1[tid] = -logf(d1 + 1e-20f) + logf(se1[tid] + 1e-20f);
        sh2[tid] = -logf(d2 + 1e-20f) + logf(se2[tid] + 1e-20f);
    }
    __syncthreads();
    if (tid == 0) {
        float a = 0.f, b = 0.f;
        for (int i = 0; i < B_SZ; i++) { a += sh1[i]; b += sh2[i]; }
        a *= (1.f / 64.f);
        b *= (1.f / 64.f);
        out[0] = 0.5f * (a + b);
        out[1] = a;
        out[2] = b;
    }
}

extern "C" void kernel_launch(void* const* d_in, const int* in_sizes, int n_in,
                              void* d_out, int out_size)
{
    const float *vision, *text;
    const unsigned char *vmask, *tmask;
    if (in_sizes[0] == N_TOT * D_K) {
        vision = (const float*)d_in[0];
        text   = (const float*)d_in[1];
    } else {
        vision = (const float*)d_in[1];
        text   = (const float*)d_in[0];
    }
    if (in_sizes[2] == N_TOT) {
        vmask = (const unsigned char*)d_in[2];
        tmask = (const unsigned char*)d_in[3];
    } else {
        vmask = (const unsigned char*)d_in[3];
        tmask = (const unsigned char*)d_in[2];
    }
    float* out = (float*)d_out;

    cudaFuncSetAttribute(gemm_max_kernel,
                         cudaFuncAttributeMaxDynamicSharedMemorySize, DSMEM_BYTES);

    const int pairs = (M_TOT + N_TOT) * D_K / 2;
    convert_kernel<<<(pairs + 255) / 256, 256>>>(text, vision);
    gemm_max_kernel<<<NT_M * NT_N, 256, DSMEM_BYTES>>>(tmask, vmask);
    dim3 mgrid(B_SZ, B_SZ);
    means_kernel<<<mgrid, 64>>>(tmask, vmask);
    finalize_kernel<<<1, 1024>>>(out);
}